// round 8
// baseline (speedup 1.0000x reference)
#include <cuda_runtime.h>
#include <cuda_bf16.h>
#include <cstdint>

#define NNODE 50000
#define NEDGE 800000
#define H 128
#define LNUM 4
#define HPAD 50048            // 391 * 128 = 782 * 64
#define NPADC 53248           // 52 * 1024, padded counts for int4 scan
#define BN_EPS 1e-5f

// split-plane smem geometry: one 32b word = bf16x2 (two consecutive k)
#define SMPH 68               // word pitch per row (64 data + 4 pad)
#define APL (64 * SMPH)       // A lo-plane offset (words)
#define WPL (128 * SMPH)      // W lo-plane offset (words)
#define WW  (2 * 128 * SMPH)  // per-matrix packed-weight words (hi+lo planes)

#define SCAN_NBLK (NPADC / 1024)   // 52

// ---------------- device scratch (allocation-free rule: __device__ globals) ---
__device__ int      g_counts[NPADC];   // pad tail beyond NNODE stays 0 forever
__device__ int      g_cursor[NNODE];
__device__ int      g_offs[NNODE + 1];
__device__ int      g_ssrc[NEDGE];
__device__ int      g_btot[SCAN_NBLK];
__device__ int      g_bbase[SCAN_NBLK];
__device__ float    g_h [(size_t)HPAD * H];
__device__ float    g_t1[(size_t)HPAD * H];
__device__ float    g_t2[(size_t)HPAD * H];
__device__ float    g_accs[8 * H];     // per-producer-GEMM stats slots
__device__ float    g_accq[8 * H];
__device__ uint32_t g_wp[9 * WW];      // pre-packed weights, two-plane smem layout

// ---------------- helpers ----------------------------------------------------
__device__ __forceinline__ float4 f4zero() { return make_float4(0.f, 0.f, 0.f, 0.f); }
__device__ __forceinline__ void f4add(float4& a, const float4 b) {
    a.x += b.x; a.y += b.y; a.z += b.z; a.w += b.w;
}
__device__ __forceinline__ float4 f4affine_relu(float4 v, float4 a, float4 s) {
    float4 r;
    r.x = fmaxf(fmaf(a.x, v.x, s.x), 0.f);
    r.y = fmaxf(fmaf(a.y, v.y, s.y), 0.f);
    r.z = fmaxf(fmaf(a.z, v.z, s.z), 0.f);
    r.w = fmaxf(fmaf(a.w, v.w, s.w), 0.f);
    return r;
}
__device__ __forceinline__ uint32_t bf2pack(__nv_bfloat16 a, __nv_bfloat16 b) {
    return (uint32_t)__bfloat16_as_ushort(a) | ((uint32_t)__bfloat16_as_ushort(b) << 16);
}
// split (x,y) into hi-pair and lo-pair bf16x2 words
__device__ __forceinline__ void split2(float x, float y, uint32_t& hw, uint32_t& lw) {
    __nv_bfloat16 hx = __float2bfloat16(x);
    __nv_bfloat16 hy = __float2bfloat16(y);
    __nv_bfloat16 lx = __float2bfloat16(x - __bfloat162float(hx));
    __nv_bfloat16 ly = __float2bfloat16(y - __bfloat162float(hy));
    hw = bf2pack(hx, hy);
    lw = bf2pack(lx, ly);
}
__device__ __forceinline__ void mma_bf16(float d[4], const uint32_t a[4],
                                         uint32_t b0, uint32_t b1) {
    asm volatile(
        "mma.sync.aligned.m16n8k16.row.col.f32.bf16.bf16.f32 "
        "{%0,%1,%2,%3}, {%4,%5,%6,%7}, {%8,%9}, {%0,%1,%2,%3};\n"
        : "+f"(d[0]), "+f"(d[1]), "+f"(d[2]), "+f"(d[3])
        : "r"(a[0]), "r"(a[1]), "r"(a[2]), "r"(a[3]), "r"(b0), "r"(b1));
}

// Inline BN-affine coefficients from a stats slot (threads t<128 write smem).
// CTYPE 1: relu(bn1(y + fc1_b)) -> a = g*rsqrt(var), s = b - mu*a   (fc bias cancels)
// CTYPE 2: relu(bn3(bn2(y + fc2_b))) -> composed analytically (b2, bn2_b cancel)
template <int CTYPE>
__device__ __forceinline__ void coef_from_slot(int t, int slot,
                                               const float* __restrict__ p0,
                                               const float* __restrict__ p1,
                                               const float* __restrict__ p2,
                                               float* ta_s, float* ts_s) {
    if (t < 128) {
        float mu = g_accs[slot * H + t] * (1.f / NNODE);
        float var = g_accq[slot * H + t] * (1.f / NNODE) - mu * mu;
        if (CTYPE == 1) {
            float a = p0[t] * rsqrtf(var + BN_EPS);
            ta_s[t] = a;
            ts_s[t] = p1[t] - mu * a;
        } else {
            float r2 = rsqrtf(var + BN_EPS);
            float gr = p0[t] * r2;
            float v3 = gr * gr * var;
            float A = gr * p1[t] * rsqrtf(v3 + BN_EPS);
            ta_s[t] = A;
            ts_s[t] = p2[t] - mu * A;
        }
    }
}

// ---------------- weight pre-packing (two-plane layout) ------------------------
// Matrices 0-3: fc1_w per layer; 4-7: fc2_w per layer; 8: fc_w.
__global__ void packw_k(const float* __restrict__ fc1_w,
                        const float* __restrict__ fc2_w,
                        const float* __restrict__ fc_w) {
    int idx = blockIdx.x * blockDim.x + threadIdx.x;
    if (idx >= 9 * 128 * 64) return;
    int m = idx / (128 * 64);
    int rem = idx - m * (128 * 64);
    int r = rem >> 6, j = rem & 63;    // row, k-pair index
    const float* src = (m < 4) ? fc1_w + (size_t)m * (H * H)
                     : (m < 8) ? fc2_w + (size_t)(m - 4) * (H * H)
                     : fc_w;
    uint32_t hw, lw;
    split2(src[r * H + 2 * j], src[r * H + 2 * j + 1], hw, lw);
    g_wp[(size_t)m * WW + r * SMPH + j]       = hw;
    g_wp[(size_t)m * WW + WPL + r * SMPH + j] = lw;
}

// ---------------- CSR build ---------------------------------------------------
__global__ void zero_k() {
    int i = blockIdx.x * blockDim.x + threadIdx.x;
    if (i < NNODE) g_counts[i] = 0;
    if (i < 8 * H) { g_accs[i] = 0.f; g_accq[i] = 0.f; }
}

__global__ void hist_k(const int* __restrict__ dst) {
    int e = blockIdx.x * blockDim.x + threadIdx.x;
    if (e < NEDGE) atomicAdd(&g_counts[dst[e]], 1);
}

// Decoupled 3-stage scan, all stages full-parallel.
__global__ void scan1_k() {
    __shared__ int wsum[8];
    int t = threadIdx.x, b = blockIdx.x;
    int4 c = *(const int4*)(g_counts + b * 1024 + t * 4);
    int s = c.x + c.y + c.z + c.w;
    #pragma unroll
    for (int d = 16; d > 0; d >>= 1) s += __shfl_xor_sync(0xffffffffu, s, d);
    if ((t & 31) == 0) wsum[t >> 5] = s;
    __syncthreads();
    if (t == 0) {
        int tot = 0;
        #pragma unroll
        for (int i = 0; i < 8; ++i) tot += wsum[i];
        g_btot[b] = tot;
    }
}

__global__ void scan2_k() {
    __shared__ int sh[64];
    int t = threadIdx.x;
    int v = (t < SCAN_NBLK) ? g_btot[t] : 0;
    sh[t] = v;
    __syncthreads();
    #pragma unroll
    for (int d = 1; d < 64; d <<= 1) {
        int y = (t >= d) ? sh[t - d] : 0;
        __syncthreads();
        sh[t] += y;
        __syncthreads();
    }
    if (t < SCAN_NBLK) g_bbase[t] = sh[t] - v;   // exclusive
}

__global__ void scan3_k() {
    __shared__ int wsum[8];
    int t = threadIdx.x, b = blockIdx.x;
    int lane = t & 31, w = t >> 5;
    int i4 = b * 1024 + t * 4;
    int4 c = *(const int4*)(g_counts + i4);
    int s0 = c.x, s1 = s0 + c.y, s2 = s1 + c.z, s3 = s2 + c.w;
    int x = s3;
    #pragma unroll
    for (int d = 1; d < 32; d <<= 1) {
        int y = __shfl_up_sync(0xffffffffu, x, d);
        if (lane >= d) x += y;
    }
    if (lane == 31) wsum[w] = x;
    __syncthreads();
    int wpre = 0;
    #pragma unroll
    for (int i = 0; i < 8; ++i) wpre += (i < w) ? wsum[i] : 0;
    int base = g_bbase[b] + wpre + x - s3;
    if (i4 + 0 < NNODE) { g_offs[i4 + 0] = base;      g_cursor[i4 + 0] = base; }
    if (i4 + 1 < NNODE) { g_offs[i4 + 1] = base + s0; g_cursor[i4 + 1] = base + s0; }
    if (i4 + 2 < NNODE) { g_offs[i4 + 2] = base + s1; g_cursor[i4 + 2] = base + s1; }
    if (i4 + 3 < NNODE) { g_offs[i4 + 3] = base + s2; g_cursor[i4 + 3] = base + s2; }
    if (b == 0 && t == 0) g_offs[NNODE] = NEDGE;
}

__global__ void fill_k(const int* __restrict__ ei) {
    int e = blockIdx.x * blockDim.x + threadIdx.x;
    if (e < NEDGE) {
        int d = ei[NEDGE + e];          // dst row of edge_index [2, E]
        int pos = atomicAdd(&g_cursor[d], 1);
        g_ssrc[pos] = ei[e];            // src
    }
}

// ---------------- aggregation: g_h = T(x_v) + sum_{j in N(v)} T(x_j) ----------
template <bool TRANS>
__global__ __launch_bounds__(256) void agg_k(const float* __restrict__ xext,
                                             int slot_in,
                                             const float* __restrict__ p0,
                                             const float* __restrict__ p1,
                                             const float* __restrict__ p2) {
    __shared__ float ta_s[128], ts_s[128];
    const float* in = TRANS ? (const float*)g_t2 : xext;
    int t = threadIdx.x;

    if (TRANS) {
        coef_from_slot<2>(t, slot_in, p0, p1, p2, ta_s, ts_s);
        __syncthreads();
    }

    int lane = t & 31;
    int node = blockIdx.x * 8 + (t >> 5);
    if (node >= HPAD) return;
    int cb = lane * 4;
    float4* outp = (float4*)(g_h + (size_t)node * H + cb);
    if (node >= NNODE) { *outp = f4zero(); return; }

    float4 Aa = f4zero(), Ss = f4zero();
    if (TRANS) {
        Aa = *(const float4*)(ta_s + cb);
        Ss = *(const float4*)(ts_s + cb);
    }

    float4 a0, a1 = f4zero(), a2 = f4zero(), a3 = f4zero();
    {
        float4 v = *(const float4*)(in + (size_t)node * H + cb);
        a0 = TRANS ? f4affine_relu(v, Aa, Ss) : v;
    }
    int j = g_offs[node];
    int jend = g_offs[node + 1];
    for (; j + 3 < jend; j += 4) {
        int s0 = g_ssrc[j], s1 = g_ssrc[j + 1], s2 = g_ssrc[j + 2], s3 = g_ssrc[j + 3];
        float4 v0 = *(const float4*)(in + (size_t)s0 * H + cb);
        float4 v1 = *(const float4*)(in + (size_t)s1 * H + cb);
        float4 v2 = *(const float4*)(in + (size_t)s2 * H + cb);
        float4 v3 = *(const float4*)(in + (size_t)s3 * H + cb);
        if (TRANS) {
            v0 = f4affine_relu(v0, Aa, Ss); v1 = f4affine_relu(v1, Aa, Ss);
            v2 = f4affine_relu(v2, Aa, Ss); v3 = f4affine_relu(v3, Aa, Ss);
        }
        f4add(a0, v0); f4add(a1, v1); f4add(a2, v2); f4add(a3, v3);
    }
    for (; j < jend; ++j) {
        float4 v = *(const float4*)(in + (size_t)g_ssrc[j] * H + cb);
        if (TRANS) v = f4affine_relu(v, Aa, Ss);
        f4add(a0, v);
    }
    f4add(a0, a1); f4add(a2, a3); f4add(a0, a2);
    *outp = a0;
}

// ---------------- tensor-core GEMM (bf16x3 split, two-plane smem) -------------
// out[n,o] = sum_k T(A[n,k]) * W[o,k]   BM=64, 2 CTAs/SM.
// 8 warps = 2(m) x 4(n); warp tile m32 x n32.  Fragments = bare LDS.32, no PRMT.
#define ASZ (2 * 64 * SMPH)                       // A hi+lo planes, words
#define GEMM_SMEM_BYTES ((ASZ + WW + 256) * 4)    // 105472

template <int CTYPE, bool STATS, bool BIAS>
__global__ __launch_bounds__(256, 2) void gemm_tc(
    int asel, int wsel, float* __restrict__ oext,
    int slot_in, int slot_out,
    const float* __restrict__ p0, const float* __restrict__ p1,
    const float* __restrict__ p2,
    const float* __restrict__ bias, int storeN) {
    const float* A = (asel == 0) ? g_h : (asel == 1) ? g_t1 : g_t2;
    float* out;
    if (BIAS) out = oext;
    else      out = (asel == 0) ? g_t1 : g_t2;

    extern __shared__ uint32_t sm[];
    uint32_t* As = sm;                    // A: hi plane [64][SMPH], lo at +APL
    uint32_t* Ws = sm + ASZ;              // W: hi plane [128][SMPH], lo at +WPL
    float* ta_s = (float*)(sm + ASZ + WW);
    float* ts_s = ta_s + 128;

    int t = threadIdx.x;
    int m0 = blockIdx.x * 64;

    if (CTYPE != 0) {
        coef_from_slot<CTYPE>(t, slot_in, p0, p1, p2, ta_s, ts_s);
        __syncthreads();
    }

    // ---- W fill: raw copy of pre-packed two-plane weights (17 x uint4) ----
    {
        const uint4* wsrc = (const uint4*)(g_wp + (size_t)wsel * WW);
        uint4* wdst = (uint4*)Ws;
        #pragma unroll
        for (int j = 0; j < 17; ++j) wdst[t + j * 256] = wsrc[t + j * 256];
    }

    // ---- A fill: 8 float4 per thread, optional affine+relu, plane-split ----
    #pragma unroll
    for (int j = 0; j < 8; ++j) {
        int idx = t + j * 256;
        int row = idx >> 5;          // 0..63
        int q = idx & 31;            // float4 index along K (k = 4q..4q+3)
        int gr = m0 + row;
        float4 v = f4zero();
        if (gr < NNODE) {
            v = *(const float4*)(A + (size_t)gr * H + q * 4);
            if (CTYPE != 0) {
                float4 a4 = *(const float4*)(ta_s + q * 4);
                float4 s4 = *(const float4*)(ts_s + q * 4);
                v = f4affine_relu(v, a4, s4);
            }
        }
        uint32_t hw0, lw0, hw1, lw1;
        split2(v.x, v.y, hw0, lw0);
        split2(v.z, v.w, hw1, lw1);
        *(uint2*)(As + row * SMPH + q * 2)       = make_uint2(hw0, hw1);
        *(uint2*)(As + APL + row * SMPH + q * 2) = make_uint2(lw0, lw1);
    }
    __syncthreads();

    int lane = t & 31;
    int w = t >> 5;
    int wm = w >> 2;         // m-warp 0..1  (rows wm*32)
    int wn = w & 3;          // n-warp 0..3  (cols wn*32)
    int g = lane >> 2;
    int tig = lane & 3;
    int mb = wm * 32;
    int nb = wn * 32;

    const uint32_t* Ah = As;
    const uint32_t* Al = As + APL;
    const uint32_t* Wh = Ws;
    const uint32_t* Wl = Ws + WPL;

    float d[2][4][4];
    #pragma unroll
    for (int mt = 0; mt < 2; ++mt)
        #pragma unroll
        for (int nt = 0; nt < 4; ++nt)
            #pragma unroll
            for (int i = 0; i < 4; ++i) d[mt][nt][i] = 0.f;

    #pragma unroll
    for (int ks = 0; ks < 8; ++ks) {
        int kb = ks * 8 + tig;       // word offset of this thread's k-pair
        uint32_t ah[2][4], al[2][4];
        #pragma unroll
        for (int mt = 0; mt < 2; ++mt) {
            int base = (mb + mt * 16 + g) * SMPH + kb;
            ah[mt][0] = Ah[base];
            ah[mt][1] = Ah[base + 8 * SMPH];
            ah[mt][2] = Ah[base + 4];
            ah[mt][3] = Ah[base + 8 * SMPH + 4];
            al[mt][0] = Al[base];
            al[mt][1] = Al[base + 8 * SMPH];
            al[mt][2] = Al[base + 4];
            al[mt][3] = Al[base + 8 * SMPH + 4];
        }
        #pragma unroll
        for (int nt = 0; nt < 4; ++nt) {
            int ob = (nb + nt * 8 + g) * SMPH + kb;
            uint32_t bh0 = Wh[ob];
            uint32_t bh1 = Wh[ob + 4];
            uint32_t bl0 = Wl[ob];
            uint32_t bl1 = Wl[ob + 4];
            #pragma unroll
            for (int mt = 0; mt < 2; ++mt) {
                mma_bf16(d[mt][nt], ah[mt], bh0, bh1);   // hi*hi
                mma_bf16(d[mt][nt], al[mt], bh0, bh1);   // lo*hi
                mma_bf16(d[mt][nt], ah[mt], bl0, bl1);   // hi*lo
            }
        }
    }

    // ---- stats: per-column sum / sumsq (padded rows contribute exact zeros) --
    if (STATS) {
        float s[4][2], q[4][2];
        #pragma unroll
        for (int nt = 0; nt < 4; ++nt)
            #pragma unroll
            for (int j = 0; j < 2; ++j) {
                float sv = 0.f, qv = 0.f;
                #pragma unroll
                for (int mt = 0; mt < 2; ++mt) {
                    float v0 = d[mt][nt][j], v1 = d[mt][nt][j + 2];
                    sv += v0 + v1;
                    qv = fmaf(v0, v0, fmaf(v1, v1, qv));
                }
                #pragma unroll
                for (int off = 4; off < 32; off <<= 1) {
                    sv += __shfl_xor_sync(0xffffffffu, sv, off);
                    qv += __shfl_xor_sync(0xffffffffu, qv, off);
                }
                s[nt][j] = sv; q[nt][j] = qv;
            }
        __syncthreads();                      // done reading As/Ws; reuse as Red
        float* RedS = (float*)sm;             // [8][32]
        float* RedQ = (float*)sm + 256;       // [8][32]
        if (g == 0) {
            #pragma unroll
            for (int nt = 0; nt < 4; ++nt)
                #pragma unroll
                for (int j = 0; j < 2; ++j) {
                    int lc = nt * 8 + tig * 2 + j;
                    RedS[w * 32 + lc] = s[nt][j];
                    RedQ[w * 32 + lc] = q[nt][j];
                }
        }
        __syncthreads();
        if (t < 128) {
            int wn2 = t >> 5;
            int lc = t & 31;
            float sv = RedS[wn2 * 32 + lc] + RedS[(wn2 + 4) * 32 + lc];
            float qv = RedQ[wn2 * 32 + lc] + RedQ[(wn2 + 4) * 32 + lc];
            atomicAdd(&g_accs[slot_out * H + t], sv);
            atomicAdd(&g_accq[slot_out * H + t], qv);
        }
    }

    // ---- store C ----
    #pragma unroll
    for (int nt = 0; nt < 4; ++nt) {
        int col = nb + nt * 8 + tig * 2;
        float2 bb = make_float2(0.f, 0.f);
        if (BIAS) bb = *(const float2*)(bias + col);
        #pragma unroll
        for (int mt = 0; mt < 2; ++mt) {
            int r0 = m0 + mb + mt * 16 + g;
            if (r0 < storeN) {
                float2 v = make_float2(d[mt][nt][0] + bb.x, d[mt][nt][1] + bb.y);
                *(float2*)(out + (size_t)r0 * H + col) = v;
            }
            if (r0 + 8 < storeN) {
                float2 v = make_float2(d[mt][nt][2] + bb.x, d[mt][nt][3] + bb.y);
                *(float2*)(out + (size_t)(r0 + 8) * H + col) = v;
            }
        }
    }
}

// ---------------- launch ------------------------------------------------------
extern "C" void kernel_launch(void* const* d_in, const int* in_sizes, int n_in,
                              void* d_out, int out_size) {
    const float* x     = (const float*)d_in[0];
    const int*   ei    = (const int*)  d_in[1];
    const float* fc1_w = (const float*)d_in[2];
    const float* bn1_g = (const float*)d_in[4];
    const float* bn1_b = (const float*)d_in[5];
    const float* fc2_w = (const float*)d_in[6];
    const float* bn2_g = (const float*)d_in[8];
    const float* bn3_g = (const float*)d_in[10];
    const float* bn3_b = (const float*)d_in[11];
    const float* fc_w  = (const float*)d_in[12];
    const float* fc_b  = (const float*)d_in[13];
    float* out = (float*)d_out;

    cudaFuncSetAttribute(gemm_tc<0, true,  false>,
                         cudaFuncAttributeMaxDynamicSharedMemorySize, GEMM_SMEM_BYTES);
    cudaFuncSetAttribute(gemm_tc<1, true,  false>,
                         cudaFuncAttributeMaxDynamicSharedMemorySize, GEMM_SMEM_BYTES);
    cudaFuncSetAttribute(gemm_tc<2, false, true >,
                         cudaFuncAttributeMaxDynamicSharedMemorySize, GEMM_SMEM_BYTES);

    zero_k<<<(NNODE + 255) / 256, 256>>>();
    packw_k<<<(9 * 128 * 64 + 255) / 256, 256>>>(fc1_w, fc2_w, fc_w);
    hist_k<<<(NEDGE + 255) / 256, 256>>>(ei + NEDGE);
    scan1_k<<<SCAN_NBLK, 256>>>();
    scan2_k<<<1, 64>>>();
    scan3_k<<<SCAN_NBLK, 256>>>();
    fill_k<<<(NEDGE + 255) / 256, 256>>>(ei);

    const int GEMM_GRID = HPAD / 64;    // 782
    const int AGG_GRID  = HPAD / 8;     // 6256

    for (int i = 0; i < LNUM; ++i) {
        if (i == 0)
            agg_k<false><<<AGG_GRID, 256>>>(x, -1, nullptr, nullptr, nullptr);
        else
            agg_k<true><<<AGG_GRID, 256>>>(nullptr, 2 * i - 1,
                                           bn2_g + (i - 1) * H, bn3_g + (i - 1) * H,
                                           bn3_b + (i - 1) * H);
        // gemm1: g_t1 = g_h @ fc1_w[i]^T, stats -> slot 2i
        gemm_tc<0, true, false><<<GEMM_GRID, 256, GEMM_SMEM_BYTES>>>(
            0, i, nullptr, -1, 2 * i,
            nullptr, nullptr, nullptr, nullptr, HPAD);
        // gemm2: g_t2 = relu(bn1-affine(g_t1)) @ fc2_w[i]^T, stats -> slot 2i+1
        gemm_tc<1, true, false><<<GEMM_GRID, 256, GEMM_SMEM_BYTES>>>(
            1, 4 + i, nullptr, 2 * i, 2 * i + 1,
            bn1_g + i * H, bn1_b + i * H, nullptr, nullptr, HPAD);
    }
    // final classifier: out = relu(bn3∘bn2-affine(g_t2)) @ fc_w^T + fc_b
    gemm_tc<2, false, true><<<GEMM_GRID, 256, GEMM_SMEM_BYTES>>>(
        2, 8, out, 7, -1,
        bn2_g + 3 * H, bn3_g + 3 * H, bn3_b + 3 * H, fc_b, NNODE);
}

// round 9
// speedup vs baseline: 1.0832x; 1.0832x over previous
#include <cuda_runtime.h>
#include <cuda_bf16.h>
#include <cstdint>

#define NNODE 50000
#define NEDGE 800000
#define H 128
#define LNUM 4
#define HPAD 50048            // 391 * 128 = 782 * 64
#define NPADC 53248           // 52 * 1024, padded counts for int4 scan
#define BN_EPS 1e-5f

#define SMP 136               // smem word pitch (8 mod 32 -> conflict-free LDS.64)
#define WWORDS (128 * SMP)    // packed weight matrix footprint (incl. pitch pad)

#define SCAN_NBLK (NPADC / 1024)   // 52
#define NTILE (HPAD / 64)          // 782
#define PGRID 296                  // persistent GEMM grid: 2 CTAs x 148 SMs

// ---------------- device scratch (allocation-free rule: __device__ globals) ---
__device__ int      g_counts[NPADC];   // pad tail beyond NNODE stays 0 forever
__device__ int      g_cursor[NNODE];
__device__ int      g_offs[NNODE + 1];
__device__ int      g_ssrc[NEDGE];
__device__ int      g_btot[SCAN_NBLK];
__device__ int      g_bbase[SCAN_NBLK];
__device__ float    g_h [(size_t)HPAD * H];
__device__ float    g_t1[(size_t)HPAD * H];
__device__ float    g_t2[(size_t)HPAD * H];
__device__ float    g_accs[8 * H];     // per-producer-GEMM stats slots
__device__ float    g_accq[8 * H];
__device__ uint32_t g_wp[9 * WWORDS];  // pre-split-packed weights, smem layout

// ---------------- helpers ----------------------------------------------------
__device__ __forceinline__ float4 f4zero() { return make_float4(0.f, 0.f, 0.f, 0.f); }
__device__ __forceinline__ void f4add(float4& a, const float4 b) {
    a.x += b.x; a.y += b.y; a.z += b.z; a.w += b.w;
}
__device__ __forceinline__ float4 f4affine_relu(float4 v, float4 a, float4 s) {
    float4 r;
    r.x = fmaxf(fmaf(a.x, v.x, s.x), 0.f);
    r.y = fmaxf(fmaf(a.y, v.y, s.y), 0.f);
    r.z = fmaxf(fmaf(a.z, v.z, s.z), 0.f);
    r.w = fmaxf(fmaf(a.w, v.w, s.w), 0.f);
    return r;
}
// split fp32 -> (bf16 hi | bf16 lo) packed in one 32-bit word (lo in high half)
__device__ __forceinline__ uint32_t pack_split(float v) {
    __nv_bfloat16 h = __float2bfloat16(v);
    float hf = __bfloat162float(h);
    __nv_bfloat16 l = __float2bfloat16(v - hf);
    return (uint32_t)__bfloat16_as_ushort(h) | ((uint32_t)__bfloat16_as_ushort(l) << 16);
}
__device__ __forceinline__ uint4 pack_split4(float4 v) {
    return make_uint4(pack_split(v.x), pack_split(v.y), pack_split(v.z), pack_split(v.w));
}
__device__ __forceinline__ void mma_bf16(float d[4], const uint32_t a[4],
                                         uint32_t b0, uint32_t b1) {
    asm volatile(
        "mma.sync.aligned.m16n8k16.row.col.f32.bf16.bf16.f32 "
        "{%0,%1,%2,%3}, {%4,%5,%6,%7}, {%8,%9}, {%0,%1,%2,%3};\n"
        : "+f"(d[0]), "+f"(d[1]), "+f"(d[2]), "+f"(d[3])
        : "r"(a[0]), "r"(a[1]), "r"(a[2]), "r"(a[3]), "r"(b0), "r"(b1));
}

// Inline BN-affine coefficients from a stats slot (threads t<128 write smem).
// CTYPE 1: relu(bn1(y + fc1_b)) -> a = g*rsqrt(var), s = b - mu*a   (fc bias cancels)
// CTYPE 2: relu(bn3(bn2(y + fc2_b))) -> composed analytically (b2, bn2_b cancel)
template <int CTYPE>
__device__ __forceinline__ void coef_from_slot(int t, int slot,
                                               const float* __restrict__ p0,
                                               const float* __restrict__ p1,
                                               const float* __restrict__ p2,
                                               float* ta_s, float* ts_s) {
    if (t < 128) {
        float mu = g_accs[slot * H + t] * (1.f / NNODE);
        float var = g_accq[slot * H + t] * (1.f / NNODE) - mu * mu;
        if (CTYPE == 1) {
            float a = p0[t] * rsqrtf(var + BN_EPS);
            ta_s[t] = a;
            ts_s[t] = p1[t] - mu * a;
        } else {
            float r2 = rsqrtf(var + BN_EPS);
            float gr = p0[t] * r2;
            float v3 = gr * gr * var;
            float A = gr * p1[t] * rsqrtf(v3 + BN_EPS);
            ta_s[t] = A;
            ts_s[t] = p2[t] - mu * A;
        }
    }
}

// ---------------- weight pre-packing ------------------------------------------
// Matrices 0-3: fc1_w per layer; 4-7: fc2_w per layer; 8: fc_w.
__global__ void packw_k(const float* __restrict__ fc1_w,
                        const float* __restrict__ fc2_w,
                        const float* __restrict__ fc_w) {
    int idx = blockIdx.x * blockDim.x + threadIdx.x;
    if (idx >= 9 * WWORDS) return;
    int m = idx / WWORDS;
    int rem = idx - m * WWORDS;
    int r = rem / SMP, c = rem - r * SMP;
    uint32_t v = 0;
    if (c < 128) {
        const float* src = (m < 4) ? fc1_w + (size_t)m * (H * H)
                         : (m < 8) ? fc2_w + (size_t)(m - 4) * (H * H)
                         : fc_w;
        v = pack_split(src[r * H + c]);
    }
    g_wp[idx] = v;
}

// ---------------- CSR build ---------------------------------------------------
__global__ void zero_k() {
    int i = blockIdx.x * blockDim.x + threadIdx.x;
    if (i < NNODE) g_counts[i] = 0;
    if (i < 8 * H) { g_accs[i] = 0.f; g_accq[i] = 0.f; }
}

__global__ void hist_k(const int* __restrict__ dst) {
    int e = blockIdx.x * blockDim.x + threadIdx.x;
    if (e < NEDGE) atomicAdd(&g_counts[dst[e]], 1);
}

// Decoupled 3-stage scan, all stages full-parallel.
__global__ void scan1_k() {
    __shared__ int wsum[8];
    int t = threadIdx.x, b = blockIdx.x;
    int4 c = *(const int4*)(g_counts + b * 1024 + t * 4);
    int s = c.x + c.y + c.z + c.w;
    #pragma unroll
    for (int d = 16; d > 0; d >>= 1) s += __shfl_xor_sync(0xffffffffu, s, d);
    if ((t & 31) == 0) wsum[t >> 5] = s;
    __syncthreads();
    if (t == 0) {
        int tot = 0;
        #pragma unroll
        for (int i = 0; i < 8; ++i) tot += wsum[i];
        g_btot[b] = tot;
    }
}

__global__ void scan2_k() {
    __shared__ int sh[64];
    int t = threadIdx.x;
    int v = (t < SCAN_NBLK) ? g_btot[t] : 0;
    sh[t] = v;
    __syncthreads();
    #pragma unroll
    for (int d = 1; d < 64; d <<= 1) {
        int y = (t >= d) ? sh[t - d] : 0;
        __syncthreads();
        sh[t] += y;
        __syncthreads();
    }
    if (t < SCAN_NBLK) g_bbase[t] = sh[t] - v;   // exclusive
}

__global__ void scan3_k() {
    __shared__ int wsum[8];
    int t = threadIdx.x, b = blockIdx.x;
    int lane = t & 31, w = t >> 5;
    int i4 = b * 1024 + t * 4;
    int4 c = *(const int4*)(g_counts + i4);
    int s0 = c.x, s1 = s0 + c.y, s2 = s1 + c.z, s3 = s2 + c.w;
    int x = s3;
    #pragma unroll
    for (int d = 1; d < 32; d <<= 1) {
        int y = __shfl_up_sync(0xffffffffu, x, d);
        if (lane >= d) x += y;
    }
    if (lane == 31) wsum[w] = x;
    __syncthreads();
    int wpre = 0;
    #pragma unroll
    for (int i = 0; i < 8; ++i) wpre += (i < w) ? wsum[i] : 0;
    int base = g_bbase[b] + wpre + x - s3;
    if (i4 + 0 < NNODE) { g_offs[i4 + 0] = base;      g_cursor[i4 + 0] = base; }
    if (i4 + 1 < NNODE) { g_offs[i4 + 1] = base + s0; g_cursor[i4 + 1] = base + s0; }
    if (i4 + 2 < NNODE) { g_offs[i4 + 2] = base + s1; g_cursor[i4 + 2] = base + s1; }
    if (i4 + 3 < NNODE) { g_offs[i4 + 3] = base + s2; g_cursor[i4 + 3] = base + s2; }
    if (b == 0 && t == 0) g_offs[NNODE] = NEDGE;
}

__global__ void fill_k(const int* __restrict__ ei) {
    int e = blockIdx.x * blockDim.x + threadIdx.x;
    if (e < NEDGE) {
        int d = ei[NEDGE + e];          // dst row of edge_index [2, E]
        int pos = atomicAdd(&g_cursor[d], 1);
        g_ssrc[pos] = ei[e];            // src
    }
}

// ---------------- aggregation: g_h = T(x_v) + sum_{j in N(v)} T(x_j) ----------
template <bool TRANS>
__global__ __launch_bounds__(256) void agg_k(const float* __restrict__ xext,
                                             int slot_in,
                                             const float* __restrict__ p0,
                                             const float* __restrict__ p1,
                                             const float* __restrict__ p2) {
    __shared__ float ta_s[128], ts_s[128];
    const float* in = TRANS ? (const float*)g_t2 : xext;
    int t = threadIdx.x;

    if (TRANS) {
        coef_from_slot<2>(t, slot_in, p0, p1, p2, ta_s, ts_s);
        __syncthreads();
    }

    int lane = t & 31;
    int node = blockIdx.x * 8 + (t >> 5);
    if (node >= HPAD) return;
    int cb = lane * 4;
    float4* outp = (float4*)(g_h + (size_t)node * H + cb);
    if (node >= NNODE) { *outp = f4zero(); return; }

    float4 Aa = f4zero(), Ss = f4zero();
    if (TRANS) {
        Aa = *(const float4*)(ta_s + cb);
        Ss = *(const float4*)(ts_s + cb);
    }

    float4 a0, a1 = f4zero(), a2 = f4zero(), a3 = f4zero();
    {
        float4 v = *(const float4*)(in + (size_t)node * H + cb);
        a0 = TRANS ? f4affine_relu(v, Aa, Ss) : v;
    }
    int j = g_offs[node];
    int jend = g_offs[node + 1];
    for (; j + 3 < jend; j += 4) {
        int s0 = g_ssrc[j], s1 = g_ssrc[j + 1], s2 = g_ssrc[j + 2], s3 = g_ssrc[j + 3];
        float4 v0 = *(const float4*)(in + (size_t)s0 * H + cb);
        float4 v1 = *(const float4*)(in + (size_t)s1 * H + cb);
        float4 v2 = *(const float4*)(in + (size_t)s2 * H + cb);
        float4 v3 = *(const float4*)(in + (size_t)s3 * H + cb);
        if (TRANS) {
            v0 = f4affine_relu(v0, Aa, Ss); v1 = f4affine_relu(v1, Aa, Ss);
            v2 = f4affine_relu(v2, Aa, Ss); v3 = f4affine_relu(v3, Aa, Ss);
        }
        f4add(a0, v0); f4add(a1, v1); f4add(a2, v2); f4add(a3, v3);
    }
    for (; j < jend; ++j) {
        float4 v = *(const float4*)(in + (size_t)g_ssrc[j] * H + cb);
        if (TRANS) v = f4affine_relu(v, Aa, Ss);
        f4add(a0, v);
    }
    f4add(a0, a1); f4add(a2, a3); f4add(a0, a2);
    *outp = a0;
}

// ---------------- persistent tensor-core GEMM (bf16x3 split, m16n8k16) --------
// out[n,o] = sum_k T(A[n,k]) * W[o,k]   BM=64, 2 CTAs/SM, PGRID persistent CTAs.
// W loaded into smem ONCE per CTA; loop over M-tiles with stride gridDim.
// 8 warps = 2(m) x 4(n); warp tile m32 x n32.
#define ASZ (64 * SMP)
#define GEMM_SMEM_BYTES ((ASZ + WWORDS + 256) * 4)

template <int CTYPE, bool STATS, bool BIAS>
__global__ __launch_bounds__(256, 2) void gemm_tc(
    int asel, int wsel, float* __restrict__ oext,
    int slot_in, int slot_out,
    const float* __restrict__ p0, const float* __restrict__ p1,
    const float* __restrict__ p2,
    const float* __restrict__ bias, int storeN) {
    const float* A = (asel == 0) ? g_h : (asel == 1) ? g_t1 : g_t2;
    float* out;
    if (BIAS) out = oext;
    else      out = (asel == 0) ? g_t1 : g_t2;

    extern __shared__ uint32_t sm[];
    uint32_t* As = sm;                    // [64][SMP] packed hi|lo
    uint32_t* Ws = sm + ASZ;              // [128][SMP]
    float* ta_s = (float*)(sm + ASZ + WWORDS);
    float* ts_s = ta_s + 128;

    int t = threadIdx.x;

    if (CTYPE != 0)
        coef_from_slot<CTYPE>(t, slot_in, p0, p1, p2, ta_s, ts_s);

    // ---- W fill ONCE: raw copy of pre-packed weights (17 x uint4/thread) ----
    {
        const uint4* wsrc = (const uint4*)(g_wp + (size_t)wsel * WWORDS);
        uint4* wdst = (uint4*)Ws;
        #pragma unroll
        for (int j = 0; j < 17; ++j) wdst[t + j * 256] = wsrc[t + j * 256];
    }

    int lane = t & 31;
    int w = t >> 5;
    int wm = w >> 2;         // m-warp 0..1  (rows wm*32)
    int wn = w & 3;          // n-warp 0..3  (cols wn*32)
    int g = lane >> 2;
    int tig = lane & 3;
    int mb = wm * 32;
    int nb = wn * 32;

    float sacc[4][2], qacc[4][2];
    if (STATS) {
        #pragma unroll
        for (int nt = 0; nt < 4; ++nt)
            #pragma unroll
            for (int j = 0; j < 2; ++j) { sacc[nt][j] = 0.f; qacc[nt][j] = 0.f; }
    }

    float2 bb[4];
    if (BIAS) {
        #pragma unroll
        for (int nt = 0; nt < 4; ++nt)
            bb[nt] = *(const float2*)(bias + nb + nt * 8 + tig * 2);
    }

    // ---- persistent tile loop ----
    for (int tile = blockIdx.x; tile < NTILE; tile += PGRID) {
        int m0 = tile * 64;
        __syncthreads();   // W/coef ready (iter 0); prior mainloop reads done (iter >0)

        // A fill: 8 float4 per thread, optional affine+relu, split-pack
        #pragma unroll
        for (int j = 0; j < 8; ++j) {
            int idx = t + j * 256;
            int row = idx >> 5;          // 0..63
            int q = idx & 31;            // float4 index along K
            int gr = m0 + row;
            float4 v = f4zero();
            if (gr < NNODE) {
                v = *(const float4*)(A + (size_t)gr * H + q * 4);
                if (CTYPE != 0) {
                    float4 a4 = *(const float4*)(ta_s + q * 4);
                    float4 s4 = *(const float4*)(ts_s + q * 4);
                    v = f4affine_relu(v, a4, s4);
                }
            }
            *(uint4*)(As + row * SMP + q * 4) = pack_split4(v);
        }
        __syncthreads();

        float d[2][4][4];
        #pragma unroll
        for (int mt = 0; mt < 2; ++mt)
            #pragma unroll
            for (int nt = 0; nt < 4; ++nt)
                #pragma unroll
                for (int i = 0; i < 4; ++i) d[mt][nt][i] = 0.f;

        #pragma unroll
        for (int ks = 0; ks < 8; ++ks) {
            int k0 = ks * 16;
            uint32_t ah[2][4], al[2][4];
            #pragma unroll
            for (int mt = 0; mt < 2; ++mt) {
                int r0 = mb + mt * 16 + g;
                uint2 w0 = *(const uint2*)(As + r0 * SMP + k0 + 2 * tig);
                uint2 w1 = *(const uint2*)(As + (r0 + 8) * SMP + k0 + 2 * tig);
                uint2 w2 = *(const uint2*)(As + r0 * SMP + k0 + 8 + 2 * tig);
                uint2 w3 = *(const uint2*)(As + (r0 + 8) * SMP + k0 + 8 + 2 * tig);
                ah[mt][0] = __byte_perm(w0.x, w0.y, 0x5410); al[mt][0] = __byte_perm(w0.x, w0.y, 0x7632);
                ah[mt][1] = __byte_perm(w1.x, w1.y, 0x5410); al[mt][1] = __byte_perm(w1.x, w1.y, 0x7632);
                ah[mt][2] = __byte_perm(w2.x, w2.y, 0x5410); al[mt][2] = __byte_perm(w2.x, w2.y, 0x7632);
                ah[mt][3] = __byte_perm(w3.x, w3.y, 0x5410); al[mt][3] = __byte_perm(w3.x, w3.y, 0x7632);
            }
            #pragma unroll
            for (int nt = 0; nt < 4; ++nt) {
                int o = nb + nt * 8 + g;
                uint2 u0 = *(const uint2*)(Ws + o * SMP + k0 + 2 * tig);
                uint2 u1 = *(const uint2*)(Ws + o * SMP + k0 + 8 + 2 * tig);
                uint32_t bh0 = __byte_perm(u0.x, u0.y, 0x5410);
                uint32_t bl0 = __byte_perm(u0.x, u0.y, 0x7632);
                uint32_t bh1 = __byte_perm(u1.x, u1.y, 0x5410);
                uint32_t bl1 = __byte_perm(u1.x, u1.y, 0x7632);
                #pragma unroll
                for (int mt = 0; mt < 2; ++mt) {
                    mma_bf16(d[mt][nt], ah[mt], bh0, bh1);   // hi*hi
                    mma_bf16(d[mt][nt], al[mt], bh0, bh1);   // lo*hi
                    mma_bf16(d[mt][nt], ah[mt], bl0, bl1);   // hi*lo
                }
            }
        }

        // stats: shuffle-reduce over m, accumulate in registers across tiles
        if (STATS) {
            #pragma unroll
            for (int nt = 0; nt < 4; ++nt)
                #pragma unroll
                for (int j = 0; j < 2; ++j) {
                    float sv = 0.f, qv = 0.f;
                    #pragma unroll
                    for (int mt = 0; mt < 2; ++mt) {
                        float v0 = d[mt][nt][j], v1 = d[mt][nt][j + 2];
                        sv += v0 + v1;
                        qv = fmaf(v0, v0, fmaf(v1, v1, qv));
                    }
                    #pragma unroll
                    for (int off = 4; off < 32; off <<= 1) {
                        sv += __shfl_xor_sync(0xffffffffu, sv, off);
                        qv += __shfl_xor_sync(0xffffffffu, qv, off);
                    }
                    sacc[nt][j] += sv; qacc[nt][j] += qv;
                }
        }

        // store C (registers only)
        #pragma unroll
        for (int nt = 0; nt < 4; ++nt) {
            int col = nb + nt * 8 + tig * 2;
            #pragma unroll
            for (int mt = 0; mt < 2; ++mt) {
                int r0 = m0 + mb + mt * 16 + g;
                if (r0 < storeN) {
                    float2 v = make_float2(d[mt][nt][0], d[mt][nt][1]);
                    if (BIAS) { v.x += bb[nt].x; v.y += bb[nt].y; }
                    *(float2*)(out + (size_t)r0 * H + col) = v;
                }
                if (r0 + 8 < storeN) {
                    float2 v = make_float2(d[mt][nt][2], d[mt][nt][3]);
                    if (BIAS) { v.x += bb[nt].x; v.y += bb[nt].y; }
                    *(float2*)(out + (size_t)(r0 + 8) * H + col) = v;
                }
            }
        }
    }

    // ---- final stats reduction: smem Red + atomics (once per CTA) ----
    if (STATS) {
        __syncthreads();                      // all mainloop smem reads done
        float* RedS = (float*)sm;             // [8][32]
        float* RedQ = (float*)sm + 256;       // [8][32]
        if (g == 0) {
            #pragma unroll
            for (int nt = 0; nt < 4; ++nt)
                #pragma unroll
                for (int j = 0; j < 2; ++j) {
                    int lc = nt * 8 + tig * 2 + j;
                    RedS[w * 32 + lc] = sacc[nt][j];
                    RedQ[w * 32 + lc] = qacc[nt][j];
                }
        }
        __syncthreads();
        if (t < 128) {
            int wn2 = t >> 5;
            int lc = t & 31;
            float sv = RedS[wn2 * 32 + lc] + RedS[(wn2 + 4) * 32 + lc];
            float qv = RedQ[wn2 * 32 + lc] + RedQ[(wn2 + 4) * 32 + lc];
            atomicAdd(&g_accs[slot_out * H + t], sv);
            atomicAdd(&g_accq[slot_out * H + t], qv);
        }
    }
}

// ---------------- launch ------------------------------------------------------
extern "C" void kernel_launch(void* const* d_in, const int* in_sizes, int n_in,
                              void* d_out, int out_size) {
    const float* x     = (const float*)d_in[0];
    const int*   ei    = (const int*)  d_in[1];
    const float* fc1_w = (const float*)d_in[2];
    const float* bn1_g = (const float*)d_in[4];
    const float* bn1_b = (const float*)d_in[5];
    const float* fc2_w = (const float*)d_in[6];
    const float* bn2_g = (const float*)d_in[8];
    const float* bn3_g = (const float*)d_in[10];
    const float* bn3_b = (const float*)d_in[11];
    const float* fc_w  = (const float*)d_in[12];
    const float* fc_b  = (const float*)d_in[13];
    float* out = (float*)d_out;

    cudaFuncSetAttribute(gemm_tc<0, true,  false>,
                         cudaFuncAttributeMaxDynamicSharedMemorySize, GEMM_SMEM_BYTES);
    cudaFuncSetAttribute(gemm_tc<1, true,  false>,
                         cudaFuncAttributeMaxDynamicSharedMemorySize, GEMM_SMEM_BYTES);
    cudaFuncSetAttribute(gemm_tc<2, false, true >,
                         cudaFuncAttributeMaxDynamicSharedMemorySize, GEMM_SMEM_BYTES);

    zero_k<<<(NNODE + 255) / 256, 256>>>();
    packw_k<<<(9 * WWORDS + 255) / 256, 256>>>(fc1_w, fc2_w, fc_w);
    hist_k<<<(NEDGE + 255) / 256, 256>>>(ei + NEDGE);
    scan1_k<<<SCAN_NBLK, 256>>>();
    scan2_k<<<1, 64>>>();
    scan3_k<<<SCAN_NBLK, 256>>>();
    fill_k<<<(NEDGE + 255) / 256, 256>>>(ei);

    const int AGG_GRID = HPAD / 8;     // 6256

    for (int i = 0; i < LNUM; ++i) {
        if (i == 0)
            agg_k<false><<<AGG_GRID, 256>>>(x, -1, nullptr, nullptr, nullptr);
        else
            agg_k<true><<<AGG_GRID, 256>>>(nullptr, 2 * i - 1,
                                           bn2_g + (i - 1) * H, bn3_g + (i - 1) * H,
                                           bn3_b + (i - 1) * H);
        // gemm1: g_t1 = g_h @ fc1_w[i]^T, stats -> slot 2i
        gemm_tc<0, true, false><<<PGRID, 256, GEMM_SMEM_BYTES>>>(
            0, i, nullptr, -1, 2 * i,
            nullptr, nullptr, nullptr, nullptr, HPAD);
        // gemm2: g_t2 = relu(bn1-affine(g_t1)) @ fc2_w[i]^T, stats -> slot 2i+1
        gemm_tc<1, true, false><<<PGRID, 256, GEMM_SMEM_BYTES>>>(
            1, 4 + i, nullptr, 2 * i, 2 * i + 1,
            bn1_g + i * H, bn1_b + i * H, nullptr, nullptr, HPAD);
    }
    // final classifier: out = relu(bn3∘bn2-affine(g_t2)) @ fc_w^T + fc_b
    gemm_tc<2, false, true><<<PGRID, 256, GEMM_SMEM_BYTES>>>(
        2, 8, out, 7, -1,
        bn2_g + 3 * H, bn3_g + 3 * H, bn3_b + 3 * H, fc_b, NNODE);
}

// round 10
// speedup vs baseline: 1.0924x; 1.0085x over previous
#include <cuda_runtime.h>
#include <cuda_bf16.h>
#include <cstdint>

#define NNODE 50000
#define NEDGE 800000
#define H 128
#define LNUM 4
#define HPAD 50048            // 391 * 128 = 782 * 64
#define NPADC 53248           // 52 * 1024, padded counts for int4 scan
#define BN_EPS 1e-5f

#define SMP 136               // smem word pitch (8 mod 32 -> conflict-free LDS.64)
#define WWORDS (128 * SMP)    // packed weight matrix footprint (incl. pitch pad)

#define SCAN_NBLK (NPADC / 1024)   // 52
#define NTILE (HPAD / 64)          // 782
#define PGRID 296                  // persistent GEMM grid: 2 CTAs x 148 SMs

// ---------------- device scratch (allocation-free rule: __device__ globals) ---
__device__ int      g_counts[NPADC];   // pad tail beyond NNODE stays 0 forever
__device__ int      g_cursor[NNODE];
__device__ int      g_offs[NNODE + 1];
__device__ int      g_ssrc[NEDGE];
__device__ int      g_btot[SCAN_NBLK];
__device__ int      g_bbase[SCAN_NBLK];
__device__ uint32_t g_h [(size_t)HPAD * H];   // agg output, ALREADY split-packed
__device__ float    g_t1[(size_t)HPAD * H];
__device__ float    g_t2[(size_t)HPAD * H];
__device__ float    g_accs[8 * H];     // per-producer-GEMM stats slots
__device__ float    g_accq[8 * H];
__device__ uint32_t g_wp[9 * WWORDS];  // pre-split-packed weights, smem layout

// ---------------- helpers ----------------------------------------------------
__device__ __forceinline__ float4 f4zero() { return make_float4(0.f, 0.f, 0.f, 0.f); }
__device__ __forceinline__ void f4add(float4& a, const float4 b) {
    a.x += b.x; a.y += b.y; a.z += b.z; a.w += b.w;
}
__device__ __forceinline__ float4 f4affine_relu(float4 v, float4 a, float4 s) {
    float4 r;
    r.x = fmaxf(fmaf(a.x, v.x, s.x), 0.f);
    r.y = fmaxf(fmaf(a.y, v.y, s.y), 0.f);
    r.z = fmaxf(fmaf(a.z, v.z, s.z), 0.f);
    r.w = fmaxf(fmaf(a.w, v.w, s.w), 0.f);
    return r;
}
// split fp32 -> (bf16 hi | bf16 lo) packed in one 32-bit word (lo in high half)
__device__ __forceinline__ uint32_t pack_split(float v) {
    __nv_bfloat16 h = __float2bfloat16(v);
    float hf = __bfloat162float(h);
    __nv_bfloat16 l = __float2bfloat16(v - hf);
    return (uint32_t)__bfloat16_as_ushort(h) | ((uint32_t)__bfloat16_as_ushort(l) << 16);
}
__device__ __forceinline__ uint4 pack_split4(float4 v) {
    return make_uint4(pack_split(v.x), pack_split(v.y), pack_split(v.z), pack_split(v.w));
}
__device__ __forceinline__ void mma_bf16(float d[4], const uint32_t a[4],
                                         uint32_t b0, uint32_t b1) {
    asm volatile(
        "mma.sync.aligned.m16n8k16.row.col.f32.bf16.bf16.f32 "
        "{%0,%1,%2,%3}, {%4,%5,%6,%7}, {%8,%9}, {%0,%1,%2,%3};\n"
        : "+f"(d[0]), "+f"(d[1]), "+f"(d[2]), "+f"(d[3])
        : "r"(a[0]), "r"(a[1]), "r"(a[2]), "r"(a[3]), "r"(b0), "r"(b1));
}

// Inline BN-affine coefficients from a stats slot (threads t<128 write smem).
// CTYPE 1: relu(bn1(y + fc1_b)) -> a = g*rsqrt(var), s = b - mu*a   (fc bias cancels)
// CTYPE 2: relu(bn3(bn2(y + fc2_b))) -> composed analytically (b2, bn2_b cancel)
template <int CTYPE>
__device__ __forceinline__ void coef_from_slot(int t, int slot,
                                               const float* __restrict__ p0,
                                               const float* __restrict__ p1,
                                               const float* __restrict__ p2,
                                               float* ta_s, float* ts_s) {
    if (t < 128) {
        float mu = g_accs[slot * H + t] * (1.f / NNODE);
        float var = g_accq[slot * H + t] * (1.f / NNODE) - mu * mu;
        if (CTYPE == 1) {
            float a = p0[t] * rsqrtf(var + BN_EPS);
            ta_s[t] = a;
            ts_s[t] = p1[t] - mu * a;
        } else {
            float r2 = rsqrtf(var + BN_EPS);
            float gr = p0[t] * r2;
            float v3 = gr * gr * var;
            float A = gr * p1[t] * rsqrtf(v3 + BN_EPS);
            ta_s[t] = A;
            ts_s[t] = p2[t] - mu * A;
        }
    }
}

// ---------------- weight pre-packing ------------------------------------------
// Matrices 0-3: fc1_w per layer; 4-7: fc2_w per layer; 8: fc_w.
__global__ void packw_k(const float* __restrict__ fc1_w,
                        const float* __restrict__ fc2_w,
                        const float* __restrict__ fc_w) {
    int idx = blockIdx.x * blockDim.x + threadIdx.x;
    if (idx >= 9 * WWORDS) return;
    int m = idx / WWORDS;
    int rem = idx - m * WWORDS;
    int r = rem / SMP, c = rem - r * SMP;
    uint32_t v = 0;
    if (c < 128) {
        const float* src = (m < 4) ? fc1_w + (size_t)m * (H * H)
                         : (m < 8) ? fc2_w + (size_t)(m - 4) * (H * H)
                         : fc_w;
        v = pack_split(src[r * H + c]);
    }
    g_wp[idx] = v;
}

// ---------------- CSR build ---------------------------------------------------
__global__ void zero_k() {
    int i = blockIdx.x * blockDim.x + threadIdx.x;
    if (i < NNODE) g_counts[i] = 0;
    if (i < 8 * H) { g_accs[i] = 0.f; g_accq[i] = 0.f; }
}

__global__ void hist_k(const int* __restrict__ dst) {
    int e = blockIdx.x * blockDim.x + threadIdx.x;
    if (e < NEDGE) atomicAdd(&g_counts[dst[e]], 1);
}

// Decoupled 3-stage scan, all stages full-parallel.
__global__ void scan1_k() {
    __shared__ int wsum[8];
    int t = threadIdx.x, b = blockIdx.x;
    int4 c = *(const int4*)(g_counts + b * 1024 + t * 4);
    int s = c.x + c.y + c.z + c.w;
    #pragma unroll
    for (int d = 16; d > 0; d >>= 1) s += __shfl_xor_sync(0xffffffffu, s, d);
    if ((t & 31) == 0) wsum[t >> 5] = s;
    __syncthreads();
    if (t == 0) {
        int tot = 0;
        #pragma unroll
        for (int i = 0; i < 8; ++i) tot += wsum[i];
        g_btot[b] = tot;
    }
}

__global__ void scan2_k() {
    __shared__ int sh[64];
    int t = threadIdx.x;
    int v = (t < SCAN_NBLK) ? g_btot[t] : 0;
    sh[t] = v;
    __syncthreads();
    #pragma unroll
    for (int d = 1; d < 64; d <<= 1) {
        int y = (t >= d) ? sh[t - d] : 0;
        __syncthreads();
        sh[t] += y;
        __syncthreads();
    }
    if (t < SCAN_NBLK) g_bbase[t] = sh[t] - v;   // exclusive
}

__global__ void scan3_k() {
    __shared__ int wsum[8];
    int t = threadIdx.x, b = blockIdx.x;
    int lane = t & 31, w = t >> 5;
    int i4 = b * 1024 + t * 4;
    int4 c = *(const int4*)(g_counts + i4);
    int s0 = c.x, s1 = s0 + c.y, s2 = s1 + c.z, s3 = s2 + c.w;
    int x = s3;
    #pragma unroll
    for (int d = 1; d < 32; d <<= 1) {
        int y = __shfl_up_sync(0xffffffffu, x, d);
        if (lane >= d) x += y;
    }
    if (lane == 31) wsum[w] = x;
    __syncthreads();
    int wpre = 0;
    #pragma unroll
    for (int i = 0; i < 8; ++i) wpre += (i < w) ? wsum[i] : 0;
    int base = g_bbase[b] + wpre + x - s3;
    if (i4 + 0 < NNODE) { g_offs[i4 + 0] = base;      g_cursor[i4 + 0] = base; }
    if (i4 + 1 < NNODE) { g_offs[i4 + 1] = base + s0; g_cursor[i4 + 1] = base + s0; }
    if (i4 + 2 < NNODE) { g_offs[i4 + 2] = base + s1; g_cursor[i4 + 2] = base + s1; }
    if (i4 + 3 < NNODE) { g_offs[i4 + 3] = base + s2; g_cursor[i4 + 3] = base + s2; }
    if (b == 0 && t == 0) g_offs[NNODE] = NEDGE;
}

__global__ void fill_k(const int* __restrict__ ei) {
    int e = blockIdx.x * blockDim.x + threadIdx.x;
    if (e < NEDGE) {
        int d = ei[NEDGE + e];          // dst row of edge_index [2, E]
        int pos = atomicAdd(&g_cursor[d], 1);
        g_ssrc[pos] = ei[e];            // src
    }
}

// ---------------- aggregation: g_h = split-pack(T(x_v) + sum T(x_j)) ----------
// Output written PRE-SPLIT for GEMM1 (same values GEMM1 would have produced;
// pack cost hides in this latency-bound kernel).  Pad rows -> zero words.
template <bool TRANS>
__global__ __launch_bounds__(256) void agg_k(const float* __restrict__ xext,
                                             int slot_in,
                                             const float* __restrict__ p0,
                                             const float* __restrict__ p1,
                                             const float* __restrict__ p2) {
    __shared__ float ta_s[128], ts_s[128];
    const float* in = TRANS ? (const float*)g_t2 : xext;
    int t = threadIdx.x;

    if (TRANS) {
        coef_from_slot<2>(t, slot_in, p0, p1, p2, ta_s, ts_s);
        __syncthreads();
    }

    int lane = t & 31;
    int node = blockIdx.x * 8 + (t >> 5);
    if (node >= HPAD) return;
    int cb = lane * 4;
    uint4* outp = (uint4*)(g_h + (size_t)node * H + cb);
    if (node >= NNODE) { *outp = make_uint4(0u, 0u, 0u, 0u); return; }

    float4 Aa = f4zero(), Ss = f4zero();
    if (TRANS) {
        Aa = *(const float4*)(ta_s + cb);
        Ss = *(const float4*)(ts_s + cb);
    }

    float4 a0, a1 = f4zero(), a2 = f4zero(), a3 = f4zero();
    {
        float4 v = *(const float4*)(in + (size_t)node * H + cb);
        a0 = TRANS ? f4affine_relu(v, Aa, Ss) : v;
    }
    int j = g_offs[node];
    int jend = g_offs[node + 1];
    for (; j + 3 < jend; j += 4) {
        int s0 = g_ssrc[j], s1 = g_ssrc[j + 1], s2 = g_ssrc[j + 2], s3 = g_ssrc[j + 3];
        float4 v0 = *(const float4*)(in + (size_t)s0 * H + cb);
        float4 v1 = *(const float4*)(in + (size_t)s1 * H + cb);
        float4 v2 = *(const float4*)(in + (size_t)s2 * H + cb);
        float4 v3 = *(const float4*)(in + (size_t)s3 * H + cb);
        if (TRANS) {
            v0 = f4affine_relu(v0, Aa, Ss); v1 = f4affine_relu(v1, Aa, Ss);
            v2 = f4affine_relu(v2, Aa, Ss); v3 = f4affine_relu(v3, Aa, Ss);
        }
        f4add(a0, v0); f4add(a1, v1); f4add(a2, v2); f4add(a3, v3);
    }
    for (; j < jend; ++j) {
        float4 v = *(const float4*)(in + (size_t)g_ssrc[j] * H + cb);
        if (TRANS) v = f4affine_relu(v, Aa, Ss);
        f4add(a0, v);
    }
    f4add(a0, a1); f4add(a2, a3); f4add(a0, a2);
    *outp = pack_split4(a0);
}

// ---------------- persistent tensor-core GEMM (bf16x3 split, m16n8k16) --------
// out[n,o] = sum_k T(A[n,k]) * W[o,k]   BM=64, 2 CTAs/SM, PGRID persistent CTAs.
// W in smem once; A prefetched into registers one tile ahead of the mainloop.
// CTYPE 0: A = g_h, already split-packed (raw copy, no guard/transform).
// CTYPE 1: A = relu(bn1-affine(g_t1)).  CTYPE 2: A = relu(bn3∘bn2-affine(g_t2)).
// 8 warps = 2(m) x 4(n); warp tile m32 x n32.
#define ASZ (64 * SMP)
#define GEMM_SMEM_BYTES ((ASZ + WWORDS + 256) * 4)

template <int CTYPE, bool STATS, bool BIAS>
__global__ __launch_bounds__(256, 2) void gemm_tc(
    int wsel, float* __restrict__ oext,
    int slot_in, int slot_out,
    const float* __restrict__ p0, const float* __restrict__ p1,
    const float* __restrict__ p2,
    const float* __restrict__ bias, int storeN) {
    const float* Af = (CTYPE == 1) ? g_t1 : g_t2;     // fp32 A (CTYPE != 0)
    float* out;
    if (BIAS) out = oext;
    else      out = (CTYPE == 0) ? g_t1 : g_t2;

    extern __shared__ uint32_t sm[];
    uint32_t* As = sm;                    // [64][SMP] packed hi|lo
    uint32_t* Ws = sm + ASZ;              // [128][SMP]
    float* ta_s = (float*)(sm + ASZ + WWORDS);
    float* ts_s = ta_s + 128;

    int t = threadIdx.x;
    int lane = t & 31;
    int w = t >> 5;

    if (CTYPE != 0)
        coef_from_slot<CTYPE>(t, slot_in, p0, p1, p2, ta_s, ts_s);

    // ---- W fill ONCE: raw copy of pre-packed weights (17 x uint4/thread) ----
    {
        const uint4* wsrc = (const uint4*)(g_wp + (size_t)wsel * WWORDS);
        uint4* wdst = (uint4*)Ws;
        #pragma unroll
        for (int j = 0; j < 17; ++j) wdst[t + j * 256] = wsrc[t + j * 256];
    }

    int wm = w >> 2;         // m-warp 0..1  (rows wm*32)
    int wn = w & 3;          // n-warp 0..3  (cols wn*32)
    int g = lane >> 2;
    int tig = lane & 3;
    int mb = wm * 32;
    int nb = wn * 32;

    float sacc[4][2], qacc[4][2];
    if (STATS) {
        #pragma unroll
        for (int nt = 0; nt < 4; ++nt)
            #pragma unroll
            for (int j = 0; j < 2; ++j) { sacc[nt][j] = 0.f; qacc[nt][j] = 0.f; }
    }

    float2 bb[4];
    if (BIAS) {
        #pragma unroll
        for (int nt = 0; nt < 4; ++nt)
            bb[nt] = *(const float2*)(bias + nb + nt * 8 + tig * 2);
    }

    // A prefetch registers: thread handles rows w + 8j (j=0..7), col block lane.
    uint4  arp[8];   // CTYPE == 0 (packed)
    float4 arf[8];   // CTYPE != 0 (fp32, pre-transform)

    int tile = blockIdx.x;
    if (tile < NTILE) {
        int m0 = tile * 64;
        #pragma unroll
        for (int j = 0; j < 8; ++j) {
            int gr = m0 + w + 8 * j;
            if (CTYPE == 0) {
                arp[j] = *(const uint4*)(g_h + (size_t)gr * H + lane * 4);
            } else {
                arf[j] = (gr < NNODE) ? *(const float4*)(Af + (size_t)gr * H + lane * 4)
                                      : f4zero();
            }
        }
    }
    __syncthreads();   // W + coefs visible

    for (; tile < NTILE; tile += PGRID) {
        int m0 = tile * 64;

        // ---- store prefetched A into smem (transform+pack if CTYPE != 0) ----
        if (CTYPE == 0) {
            #pragma unroll
            for (int j = 0; j < 8; ++j)
                *(uint4*)(As + (w + 8 * j) * SMP + lane * 4) = arp[j];
        } else {
            float4 a4 = *(const float4*)(ta_s + lane * 4);
            float4 s4 = *(const float4*)(ts_s + lane * 4);
            #pragma unroll
            for (int j = 0; j < 8; ++j) {
                int gr = m0 + w + 8 * j;
                float4 v = (gr < NNODE) ? f4affine_relu(arf[j], a4, s4) : f4zero();
                *(uint4*)(As + (w + 8 * j) * SMP + lane * 4) = pack_split4(v);
            }
        }
        __syncthreads();

        // ---- prefetch next tile's A (overlaps with mainloop below) ----
        int nxt = tile + PGRID;
        if (nxt < NTILE) {
            int n0 = nxt * 64;
            #pragma unroll
            for (int j = 0; j < 8; ++j) {
                int gr = n0 + w + 8 * j;
                if (CTYPE == 0) {
                    arp[j] = *(const uint4*)(g_h + (size_t)gr * H + lane * 4);
                } else {
                    arf[j] = (gr < NNODE) ? *(const float4*)(Af + (size_t)gr * H + lane * 4)
                                          : f4zero();
                }
            }
        }

        // ---- mainloop ----
        float d[2][4][4];
        #pragma unroll
        for (int mt = 0; mt < 2; ++mt)
            #pragma unroll
            for (int nt = 0; nt < 4; ++nt)
                #pragma unroll
                for (int i = 0; i < 4; ++i) d[mt][nt][i] = 0.f;

        #pragma unroll
        for (int ks = 0; ks < 8; ++ks) {
            int k0 = ks * 16;
            uint32_t ah[2][4], al[2][4];
            #pragma unroll
            for (int mt = 0; mt < 2; ++mt) {
                int r0 = mb + mt * 16 + g;
                uint2 w0 = *(const uint2*)(As + r0 * SMP + k0 + 2 * tig);
                uint2 w1 = *(const uint2*)(As + (r0 + 8) * SMP + k0 + 2 * tig);
                uint2 w2 = *(const uint2*)(As + r0 * SMP + k0 + 8 + 2 * tig);
                uint2 w3 = *(const uint2*)(As + (r0 + 8) * SMP + k0 + 8 + 2 * tig);
                ah[mt][0] = __byte_perm(w0.x, w0.y, 0x5410); al[mt][0] = __byte_perm(w0.x, w0.y, 0x7632);
                ah[mt][1] = __byte_perm(w1.x, w1.y, 0x5410); al[mt][1] = __byte_perm(w1.x, w1.y, 0x7632);
                ah[mt][2] = __byte_perm(w2.x, w2.y, 0x5410); al[mt][2] = __byte_perm(w2.x, w2.y, 0x7632);
                ah[mt][3] = __byte_perm(w3.x, w3.y, 0x5410); al[mt][3] = __byte_perm(w3.x, w3.y, 0x7632);
            }
            #pragma unroll
            for (int nt = 0; nt < 4; ++nt) {
                int o = nb + nt * 8 + g;
                uint2 u0 = *(const uint2*)(Ws + o * SMP + k0 + 2 * tig);
                uint2 u1 = *(const uint2*)(Ws + o * SMP + k0 + 8 + 2 * tig);
                uint32_t bh0 = __byte_perm(u0.x, u0.y, 0x5410);
                uint32_t bl0 = __byte_perm(u0.x, u0.y, 0x7632);
                uint32_t bh1 = __byte_perm(u1.x, u1.y, 0x5410);
                uint32_t bl1 = __byte_perm(u1.x, u1.y, 0x7632);
                #pragma unroll
                for (int mt = 0; mt < 2; ++mt) {
                    mma_bf16(d[mt][nt], ah[mt], bh0, bh1);   // hi*hi
                    mma_bf16(d[mt][nt], al[mt], bh0, bh1);   // lo*hi
                    mma_bf16(d[mt][nt], ah[mt], bl0, bl1);   // hi*lo
                }
            }
        }

        // ---- stats: shuffle-reduce over m, accumulate across tiles ----
        if (STATS) {
            #pragma unroll
            for (int nt = 0; nt < 4; ++nt)
                #pragma unroll
                for (int j = 0; j < 2; ++j) {
                    float sv = 0.f, qv = 0.f;
                    #pragma unroll
                    for (int mt = 0; mt < 2; ++mt) {
                        float v0 = d[mt][nt][j], v1 = d[mt][nt][j + 2];
                        sv += v0 + v1;
                        qv = fmaf(v0, v0, fmaf(v1, v1, qv));
                    }
                    #pragma unroll
                    for (int off = 4; off < 32; off <<= 1) {
                        sv += __shfl_xor_sync(0xffffffffu, sv, off);
                        qv += __shfl_xor_sync(0xffffffffu, qv, off);
                    }
                    sacc[nt][j] += sv; qacc[nt][j] += qv;
                }
        }

        // ---- store C ----
        #pragma unroll
        for (int nt = 0; nt < 4; ++nt) {
            int col = nb + nt * 8 + tig * 2;
            #pragma unroll
            for (int mt = 0; mt < 2; ++mt) {
                int r0 = m0 + mb + mt * 16 + g;
                if (r0 < storeN) {
                    float2 v = make_float2(d[mt][nt][0], d[mt][nt][1]);
                    if (BIAS) { v.x += bb[nt].x; v.y += bb[nt].y; }
                    *(float2*)(out + (size_t)r0 * H + col) = v;
                }
                if (r0 + 8 < storeN) {
                    float2 v = make_float2(d[mt][nt][2], d[mt][nt][3]);
                    if (BIAS) { v.x += bb[nt].x; v.y += bb[nt].y; }
                    *(float2*)(out + (size_t)(r0 + 8) * H + col) = v;
                }
            }
        }
        __syncthreads();   // all As reads done before next iteration's store
    }

    // ---- final stats reduction: smem Red + atomics (once per CTA) ----
    if (STATS) {
        float* RedS = (float*)sm;             // [8][32]
        float* RedQ = (float*)sm + 256;       // [8][32]
        if (g == 0) {
            #pragma unroll
            for (int nt = 0; nt < 4; ++nt)
                #pragma unroll
                for (int j = 0; j < 2; ++j) {
                    int lc = nt * 8 + tig * 2 + j;
                    RedS[w * 32 + lc] = sacc[nt][j];
                    RedQ[w * 32 + lc] = qacc[nt][j];
                }
        }
        __syncthreads();
        if (t < 128) {
            int wn2 = t >> 5;
            int lc = t & 31;
            float sv = RedS[wn2 * 32 + lc] + RedS[(wn2 + 4) * 32 + lc];
            float qv = RedQ[wn2 * 32 + lc] + RedQ[(wn2 + 4) * 32 + lc];
            atomicAdd(&g_accs[slot_out * H + t], sv);
            atomicAdd(&g_accq[slot_out * H + t], qv);
        }
    }
}

// ---------------- launch ------------------------------------------------------
extern "C" void kernel_launch(void* const* d_in, const int* in_sizes, int n_in,
                              void* d_out, int out_size) {
    const float* x     = (const float*)d_in[0];
    const int*   ei    = (const int*)  d_in[1];
    const float* fc1_w = (const float*)d_in[2];
    const float* bn1_g = (const float*)d_in[4];
    const float* bn1_b = (const float*)d_in[5];
    const float* fc2_w = (const float*)d_in[6];
    const float* bn2_g = (const float*)d_in[8];
    const float* bn3_g = (const float*)d_in[10];
    const float* bn3_b = (const float*)d_in[11];
    const float* fc_w  = (const float*)d_in[12];
    const float* fc_b  = (const float*)d_in[13];
    float* out = (float*)d_out;

    cudaFuncSetAttribute(gemm_tc<0, true,  false>,
                         cudaFuncAttributeMaxDynamicSharedMemorySize, GEMM_SMEM_BYTES);
    cudaFuncSetAttribute(gemm_tc<1, true,  false>,
                         cudaFuncAttributeMaxDynamicSharedMemorySize, GEMM_SMEM_BYTES);
    cudaFuncSetAttribute(gemm_tc<2, false, true >,
                         cudaFuncAttributeMaxDynamicSharedMemorySize, GEMM_SMEM_BYTES);

    zero_k<<<(NNODE + 255) / 256, 256>>>();
    packw_k<<<(9 * WWORDS + 255) / 256, 256>>>(fc1_w, fc2_w, fc_w);
    hist_k<<<(NEDGE + 255) / 256, 256>>>(ei + NEDGE);
    scan1_k<<<SCAN_NBLK, 256>>>();
    scan2_k<<<1, 64>>>();
    scan3_k<<<SCAN_NBLK, 256>>>();
    fill_k<<<(NEDGE + 255) / 256, 256>>>(ei);

    const int AGG_GRID = HPAD / 8;     // 6256

    for (int i = 0; i < LNUM; ++i) {
        if (i == 0)
            agg_k<false><<<AGG_GRID, 256>>>(x, -1, nullptr, nullptr, nullptr);
        else
            agg_k<true><<<AGG_GRID, 256>>>(nullptr, 2 * i - 1,
                                           bn2_g + (i - 1) * H, bn3_g + (i - 1) * H,
                                           bn3_b + (i - 1) * H);
        // gemm1: g_t1 = g_h @ fc1_w[i]^T, stats -> slot 2i
        gemm_tc<0, true, false><<<PGRID, 256, GEMM_SMEM_BYTES>>>(
            i, nullptr, -1, 2 * i,
            nullptr, nullptr, nullptr, nullptr, HPAD);
        // gemm2: g_t2 = relu(bn1-affine(g_t1)) @ fc2_w[i]^T, stats -> slot 2i+1
        gemm_tc<1, true, false><<<PGRID, 256, GEMM_SMEM_BYTES>>>(
            4 + i, nullptr, 2 * i, 2 * i + 1,
            bn1_g + i * H, bn1_b + i * H, nullptr, nullptr, HPAD);
    }
    // final classifier: out = relu(bn3∘bn2-affine(g_t2)) @ fc_w^T + fc_b
    gemm_tc<2, false, true><<<PGRID, 256, GEMM_SMEM_BYTES>>>(
        8, out, 7, -1,
        bn2_g + 3 * H, bn3_g + 3 * H, bn3_b + 3 * H, fc_b, NNODE);
}